// round 14
// baseline (speedup 1.0000x reference)
#include <cuda_runtime.h>
#include <cuda_bf16.h>
#include <cstdint>

// ---------------------------------------------------------------------------
// TransIFF encoder: 2-layer deformable-box-attention transformer encoder.
// B=1, H=W=128 -> L=16384 tokens, D=256, NH=8, HD=32, K2=25, DFF=1024.
// Round 14: R12 base (ldmatrix A+B, k-octet weights, dual projection GEMM)
// + 3-stage cp.async pipeline (prefetch distance 2, occupancy preserved).
// tcgen05 is unavailable in this toolchain (compute_103 PTX target).
// ---------------------------------------------------------------------------

namespace {
constexpr int L    = 16384;
constexpr int D    = 256;
constexpr int NH   = 8;
constexpr int HD   = 32;
constexpr int K2   = 25;
constexpr int DFF  = 1024;
constexpr int HDIM = 128;
constexpr int WDIM = 128;
constexpr float EPS = 1e-5f;

constexpr int NCAT  = NH * K2 + NH * 4;  // 232 real cols
constexpr int NCATP = 256;               // padded for bf16 GEMM

// ---- bf16 GEMM tiling ----
constexpr int BM = 128, BN = 128;
constexpr int HBK   = 64;
constexpr int HASTR = 36;                  // A words/row: 32 data + 4 pad
constexpr int HBSTR = 520;                 // B words/chunk-row: 128 cells*4 + 8 pad
constexpr int HASIZE = BM * HASTR;         // 4608 words
constexpr int HBSIZE = (HBK / 8) * HBSTR;  // 4160 words
constexpr int HSTAGE = HASIZE + HBSIZE;    // 8768 words
constexpr int NSTG   = 3;
constexpr int HGEMM_SMEM = NSTG * HSTAGE * 4; // 105216 B (2 CTAs/SM: 210KB < 228KB)

// ---- sampler tiling ----
constexpr int TS   = 16;
constexpr int PAD  = 3;
constexpr int PW   = TS + 2 * PAD;   // 22
constexpr int SAMP_SMEM = PW * PW * HD * 4;          // 61952 B
}

// ------------------------- scratch (device globals) -----------------------
__device__ float g_X[L * D];
__device__ float g_P[L * D];
__device__ float g_VAL[L * D];
__device__ float g_TMP[L * D];
__device__ float g_AWOFF[L * NCATP];
__device__ float g_BCAT[2 * NCATP];
__device__ __nv_bfloat16 g_Qh[L * D];
__device__ __nv_bfloat16 g_OUTh[L * D];
__device__ __nv_bfloat16 g_Xh[L * D];
__device__ __nv_bfloat16 g_FFh[L * DFF];
__device__ __nv_bfloat16 g_WCATh[2 * D * NCATP];   // k-octet layout [D/8][NCATP][8]
__device__ __nv_bfloat16 g_W1h[2 * D * DFF];
__device__ __nv_bfloat16 g_W2h[2 * DFF * D];
__device__ __nv_bfloat16 g_Woh[2 * D * D];
__device__ __nv_bfloat16 g_Wvh[2 * D * D];

// ------------------------- PTX helpers ------------------------------------
__device__ __forceinline__ uint32_t smem_u32(const void* p) {
    return (uint32_t)__cvta_generic_to_shared(p);
}
__device__ __forceinline__ void cp_async16(uint32_t saddr, const void* gaddr) {
    asm volatile("cp.async.ca.shared.global [%0], [%1], 16;\n" :: "r"(saddr), "l"(gaddr));
}
__device__ __forceinline__ void cp_commit() { asm volatile("cp.async.commit_group;\n"); }
template <int NG>
__device__ __forceinline__ void cp_wait() { asm volatile("cp.async.wait_group %0;\n" :: "n"(NG)); }

__device__ __forceinline__ void mma_bf16(float d[4], const uint32_t a[4], const uint32_t b[2]) {
    asm volatile(
        "mma.sync.aligned.m16n8k16.row.col.f32.bf16.bf16.f32 "
        "{%0,%1,%2,%3}, {%4,%5,%6,%7}, {%8,%9}, {%0,%1,%2,%3};\n"
        : "+f"(d[0]), "+f"(d[1]), "+f"(d[2]), "+f"(d[3])
        : "r"(a[0]), "r"(a[1]), "r"(a[2]), "r"(a[3]), "r"(b[0]), "r"(b[1]));
}
__device__ __forceinline__ void ldsm_x4(uint32_t r[4], uint32_t saddr) {
    asm volatile("ldmatrix.sync.aligned.m8n8.x4.shared.b16 {%0,%1,%2,%3}, [%4];"
                 : "=r"(r[0]), "=r"(r[1]), "=r"(r[2]), "=r"(r[3]) : "r"(saddr));
}

// ------------------------- bf16 tensor-core GEMM body ----------------------
// C[M,N] = A[M,K] @ B[K,N] (+bias)(+relu). A row-major bf16. Bo: k-octet
// interleaved bf16 [K/8][N][8]. M%128==0, N%128==0, K%64==0.
// A and B fragments via ldmatrix.x4; 3-stage cp.async pipeline.
// EPI: 1 = fp32+bias ; 2 = bf16+bias+relu.
template <int EPI>
__device__ __forceinline__ void
hmma_gemm_body(const __nv_bfloat16* __restrict__ A, const __nv_bfloat16* __restrict__ Bo,
               const float* __restrict__ bias, void* __restrict__ Cout,
               int M, int N, int K, int bm, int bn, uint32_t* smem) {
    const int tid  = threadIdx.x;
    const int warp = tid >> 5;
    const int lane = tid & 31;
    const int g    = lane >> 2;
    const int t    = lane & 3;
    const int wm   = warp & 1;
    const int wn   = warp >> 1;

    auto load_tile = [&](int stage, int k0) {
        uint32_t abase = smem_u32(smem + stage * HSTAGE);
#pragma unroll
        for (int it = 0; it < 4; it++) {
            int id = tid + it * 256;
            int r = id >> 3;
            int c = id & 7;
            cp_async16(abase + (r * HASTR + c * 4) * 4,
                       A + (size_t)(bm + r) * K + k0 + c * 8);
        }
        uint32_t bbase = smem_u32(smem + stage * HSTAGE + HASIZE);
#pragma unroll
        for (int it = 0; it < 4; it++) {
            int id = tid + it * 256;
            int chunk = id >> 7;       // 0..7 (HBK/8)
            int n     = id & 127;      // 0..127
            cp_async16(bbase + (chunk * HBSTR + n * 4) * 4,
                       Bo + ((size_t)(k0 / 8 + chunk) * N + bn + n) * 8);
        }
    };

    // ldmatrix lane address components
    const int lrow  = lane & 15;               // A: row within 16-row frag
    const int koff  = ((lane >> 4) & 1) * 4;   // A: word offset for k+8 half
    const int bnsel = ((lane >> 4) & 1) * 8 + (lane & 7);  // B: col within 16
    const int bcsel = (lane >> 3) & 1;                     // B: chunk 0/1

    float acc[4][4][4] = {};

    const int nk = K / HBK;
    // prologue: prefetch up to 2 tiles
    load_tile(0, 0);
    cp_commit();
    if (nk > 1) { load_tile(1, HBK); cp_commit(); }

    for (int kt = 0; kt < nk; kt++) {
        // tiles committed so far: min(kt+2, nk). Need tile kt complete.
        if (kt + 2 <= nk - 1 + 1 && kt + 2 <= nk) {
            // rem = committed - (kt+1)
        }
        if (kt + 1 < nk) cp_wait<1>();   // newest (tile kt+1) may be in flight
        else             cp_wait<0>();   // last tile: drain fully
        __syncthreads();
        // prefetch tile kt+2 into stage (kt+2)%3 = (kt-1)%3, whose readers
        // finished at iteration kt-1 (guaranteed by the sync above).
        if (kt + 2 < nk) { load_tile((kt + 2) % NSTG, (kt + 2) * HBK); cp_commit(); }

        const uint32_t* Ac = smem + (kt % NSTG) * HSTAGE;
        const uint32_t AcAddr = smem_u32(Ac);
        const uint32_t BcAddr = smem_u32(Ac + HASIZE);
        uint32_t arow[4];
#pragma unroll
        for (int mt = 0; mt < 4; mt++) {
            int row = wm * 64 + mt * 16 + lrow;
            arow[mt] = AcAddr + (row * HASTR + koff) * 4;
        }
        const uint32_t bbase0 = BcAddr + (bcsel * HBSTR + (wn * 32 + bnsel) * 4) * 4;
        const uint32_t bbase1 = bbase0 + 16 * 4 * 4;   // cols +16

#pragma unroll
        for (int k16 = 0; k16 < HBK; k16 += 16) {
            const int kw = k16 >> 1;        // A word offset
            const int kc = k16 >> 3;        // B chunk base (0,2,4,6)
            uint32_t af[4][4], bf0[4], bf1[4];
#pragma unroll
            for (int mt = 0; mt < 4; mt++)
                ldsm_x4(af[mt], arow[mt] + kw * 4);
            ldsm_x4(bf0, bbase0 + kc * HBSTR * 4);   // nt 0,1
            ldsm_x4(bf1, bbase1 + kc * HBSTR * 4);   // nt 2,3
            uint32_t bf[4][2] = {{bf0[0], bf0[1]}, {bf0[2], bf0[3]},
                                 {bf1[0], bf1[1]}, {bf1[2], bf1[3]}};
#pragma unroll
            for (int mt = 0; mt < 4; mt++)
#pragma unroll
                for (int nt = 0; nt < 4; nt++)
                    mma_bf16(acc[mt][nt], af[mt], bf[nt]);
        }
    }

#pragma unroll
    for (int mt = 0; mt < 4; mt++) {
        int r0 = bm + wm * 64 + mt * 16 + g;
#pragma unroll
        for (int nt = 0; nt < 4; nt++) {
            int col = bn + wn * 32 + nt * 8 + 2 * t;
            float b0 = bias[col], b1 = bias[col + 1];
            float v0 = acc[mt][nt][0] + b0;
            float v1 = acc[mt][nt][1] + b1;
            float v2 = acc[mt][nt][2] + b0;
            float v3 = acc[mt][nt][3] + b1;
            if (EPI == 2) {
                v0 = fmaxf(v0, 0.f); v1 = fmaxf(v1, 0.f);
                v2 = fmaxf(v2, 0.f); v3 = fmaxf(v3, 0.f);
                __nv_bfloat16* C = (__nv_bfloat16*)Cout;
                *(__nv_bfloat162*)(C + (size_t)r0 * N + col)       = __floats2bfloat162_rn(v0, v1);
                *(__nv_bfloat162*)(C + (size_t)(r0 + 8) * N + col) = __floats2bfloat162_rn(v2, v3);
            } else {
                float* C = (float*)Cout;
                *(float2*)(C + (size_t)r0 * N + col)       = make_float2(v0, v1);
                *(float2*)(C + (size_t)(r0 + 8) * N + col) = make_float2(v2, v3);
            }
        }
    }
}

template <int EPI>
__global__ void __launch_bounds__(256, 2)
hmma_gemm_kernel(const __nv_bfloat16* __restrict__ A, const __nv_bfloat16* __restrict__ Bo,
                 const float* __restrict__ bias, void* __restrict__ Cout,
                 int M, int N, int K) {
    extern __shared__ uint32_t smem[];
    hmma_gemm_body<EPI>(A, Bo, bias, Cout, M, N, K,
                        blockIdx.y * BM, blockIdx.x * BN, smem);
}

// Dual GEMM: blockIdx.z selects problem (same M, N, K, EPI=1).
__global__ void __launch_bounds__(256, 2)
hmma_gemm_dual_kernel(const __nv_bfloat16* __restrict__ A0, const __nv_bfloat16* __restrict__ B0,
                      const float* __restrict__ bias0, void* __restrict__ C0,
                      const __nv_bfloat16* __restrict__ A1, const __nv_bfloat16* __restrict__ B1,
                      const float* __restrict__ bias1, void* __restrict__ C1,
                      int M, int N, int K) {
    extern __shared__ uint32_t smem[];
    if (blockIdx.z == 0)
        hmma_gemm_body<1>(A0, B0, bias0, C0, M, N, K,
                          blockIdx.y * BM, blockIdx.x * BN, smem);
    else
        hmma_gemm_body<1>(A1, B1, bias1, C1, M, N, K,
                          blockIdx.y * BM, blockIdx.x * BN, smem);
}

// ------ all-weights convert: fp32 -> bf16 k-octet interleaved, 1 launch ----
// seg: 0,1 = W1 (K=D,N=DFF); 2,3 = W2 (K=DFF,N=D); 4,5 = Wo; 6,7 = Wv.
// out[((k/8)*N + n)*8 + k%8] = in[k][n]
__global__ void convert_all_kernel(const float* __restrict__ W1, const float* __restrict__ W2,
                                   const float* __restrict__ Wo, const float* __restrict__ Wv,
                                   __nv_bfloat16* __restrict__ W1h,
                                   __nv_bfloat16* __restrict__ W2h,
                                   __nv_bfloat16* __restrict__ Woh,
                                   __nv_bfloat16* __restrict__ Wvh) {
    int seg = blockIdx.y;
    int Kdim, Ndim;
    const float* W;
    __nv_bfloat16* Wh;
    if (seg < 2)      { Kdim = D;   Ndim = DFF; W = W1 + (size_t)seg * D * DFF;       Wh = W1h + (size_t)seg * D * DFF; }
    else if (seg < 4) { Kdim = DFF; Ndim = D;   W = W2 + (size_t)(seg - 2) * DFF * D; Wh = W2h + (size_t)(seg - 2) * DFF * D; }
    else if (seg < 6) { Kdim = D;   Ndim = D;   W = Wo + (size_t)(seg - 4) * D * D;   Wh = Woh + (size_t)(seg - 4) * D * D; }
    else              { Kdim = D;   Ndim = D;   W = Wv + (size_t)(seg - 6) * D * D;   Wh = Wvh + (size_t)(seg - 6) * D * D; }
    int i = blockIdx.x * blockDim.x + threadIdx.x;
    int total = (Kdim / 8) * Ndim;
    if (i >= total) return;
    int chunk = i / Ndim, n = i % Ndim;
    __nv_bfloat162 o[4];
#pragma unroll
    for (int j = 0; j < 4; j++) {
        float a = W[(size_t)(chunk * 8 + 2 * j)     * Ndim + n];
        float b = W[(size_t)(chunk * 8 + 2 * j + 1) * Ndim + n];
        o[j] = __floats2bfloat162_rn(a, b);
    }
    uint4 v;
    v.x = *(uint32_t*)&o[0]; v.y = *(uint32_t*)&o[1];
    v.z = *(uint32_t*)&o[2]; v.w = *(uint32_t*)&o[3];
    *(uint4*)(Wh + (size_t)i * 8) = v;
}

// ------ merged attn+box weights -> bf16 k-octet, padded to 256, 2 layers ---
__global__ void concat_wb_bf16_kernel(const float* __restrict__ Wattn, const float* __restrict__ battn,
                                      const float* __restrict__ Wbox,  const float* __restrict__ bbox,
                                      __nv_bfloat16* __restrict__ WCh, float* __restrict__ BC) {
    int chunk = blockIdx.x;
    int li    = blockIdx.y;
    int n     = threadIdx.x;
    const float* Wa = Wattn + (size_t)li * D * (NH * K2);
    const float* Wb = Wbox  + (size_t)li * D * (NH * 4);
    __nv_bfloat162 o[4];
#pragma unroll
    for (int j = 0; j < 4; j++) {
        float a = 0.f, b = 0.f;
        int k0 = chunk * 8 + 2 * j;
        if (n < NH * K2) {
            a = Wa[(size_t)k0 * (NH * K2) + n];
            b = Wa[(size_t)(k0 + 1) * (NH * K2) + n];
        } else if (n < NCAT) {
            a = Wb[(size_t)k0 * (NH * 4) + (n - NH * K2)];
            b = Wb[(size_t)(k0 + 1) * (NH * 4) + (n - NH * K2)];
        }
        o[j] = __floats2bfloat162_rn(a, b);
    }
    uint4 v;
    v.x = *(uint32_t*)&o[0]; v.y = *(uint32_t*)&o[1];
    v.z = *(uint32_t*)&o[2]; v.w = *(uint32_t*)&o[3];
    *(uint4*)(WCh + ((size_t)li * (D / 8) * NCATP + (size_t)chunk * NCATP + n) * 8) = v;
    if (chunk == 0) {
        const float* ba = battn + (size_t)li * (NH * K2);
        const float* bb = bbox  + (size_t)li * (NH * 4);
        BC[li * NCATP + n] = (n < NH * K2) ? ba[n] : (n < NCAT ? bb[n - NH * K2] : 0.f);
    }
}

// --- fused transpose: (D,L)x2 -> X, P, Qh=bf16(X+P), Xh=bf16(X) (L,D) ------
__global__ void transpose2_kernel(const float* __restrict__ S, const float* __restrict__ Pp,
                                  float* __restrict__ X, float* __restrict__ P,
                                  __nv_bfloat16* __restrict__ Qh,
                                  __nv_bfloat16* __restrict__ Xh) {
    __shared__ float ts[32][33];
    __shared__ float tp[32][33];
    int bx = blockIdx.x * 32;
    int by = blockIdx.y * 32;
    int tx = threadIdx.x, ty = threadIdx.y;
#pragma unroll
    for (int j = 0; j < 32; j += 8) {
        ts[ty + j][tx] = S [(size_t)(by + ty + j) * L + bx + tx];
        tp[ty + j][tx] = Pp[(size_t)(by + ty + j) * L + bx + tx];
    }
    __syncthreads();
#pragma unroll
    for (int j = 0; j < 32; j += 8) {
        size_t o = (size_t)(bx + ty + j) * D + by + tx;
        float xs = ts[tx][ty + j];
        float ps = tp[tx][ty + j];
        X[o] = xs;
        P[o] = ps;
        Qh[o] = __float2bfloat16_rn(xs + ps);
        Xh[o] = __float2bfloat16_rn(xs);
    }
}

// ------------- smem-tiled deformable box sampling + fused softmax ----------
__global__ void __launch_bounds__(256, 3)
box_sample_tiled_kernel(const float* __restrict__ VAL,
                        const float* __restrict__ AWOFF,
                        __nv_bfloat16* __restrict__ OUT) {
    extern __shared__ float patch[];   // [PW*PW][32]

    const int tile = blockIdx.x;
    const int h    = blockIdx.y;
    const int tx0  = (tile & 7) * TS;
    const int ty0  = (tile >> 3) * TS;
    const int xlo  = tx0 - PAD;
    const int ylo  = ty0 - PAD;
    const int tid  = threadIdx.x;
    const int warp = tid >> 5;
    const int lane = tid & 31;

    for (int i = tid; i < PW * PW * (HD / 4); i += 256) {
        int pix = i >> 3;
        int c4  = (i & 7) * 4;
        int py  = pix / PW, px = pix % PW;
        int gy  = min(max(ylo + py, 0), HDIM - 1);
        int gx  = min(max(xlo + px, 0), WDIM - 1);
        float4 v = *(const float4*)(VAL + (size_t)(gy * WDIM + gx) * D + h * HD + c4);
        *(float4*)(patch + pix * HD + c4) = v;
    }
    __syncthreads();

    const float* vbase = VAL + h * HD + lane;
    const float scl = 0.025f * 0.125f;

    for (int it = 0; it < 32; it++) {
        int tt = warp * 32 + it;
        int r = tt >> 4, c = tt & 15;
        int gx = tx0 + c, gy = ty0 + r;
        int l = gy * WDIM + gx;

        const float* awl = AWOFF + (size_t)l * NCATP + h * K2;
        float lg = (lane < K2) ? awl[lane] : -1e30f;
        float mx = lg;
#pragma unroll
        for (int o = 16; o; o >>= 1) mx = fmaxf(mx, __shfl_xor_sync(0xFFFFFFFFu, mx, o));
        float e = (lane < K2) ? __expf(lg - mx) : 0.f;
        float s = e;
#pragma unroll
        for (int o = 16; o; o >>= 1) s += __shfl_xor_sync(0xFFFFFFFFu, s, o);
        float wsm = e / s;

        const float* off = AWOFF + (size_t)l * NCATP + NH * K2 + h * 4;
        float bx = (gx + 0.5f) * (1.f / WDIM) + off[0] * scl;
        float by = (gy + 0.5f) * (1.f / HDIM) + off[1] * scl;
        float bw = 0.025f + off[2] * scl;
        float bh = 0.025f + off[3] * scl;

        float acc = 0.f;
#pragma unroll
        for (int k = 0; k < K2; k++) {
            float a = __shfl_sync(0xFFFFFFFFu, wsm, k);
            float gxk = -0.5f + 0.25f * (k % 5);
            float gyk = -0.5f + 0.25f * (k / 5);
            float px = (bx + bw * gxk) * (float)WDIM - 0.5f;
            float py = (by + bh * gyk) * (float)HDIM - 0.5f;
            int ix0 = (int)floorf(px);
            int iy0 = (int)floorf(py);
            float fx = px - (float)ix0;
            float fy = py - (float)iy0;

            int lx = ix0 - xlo, ly = iy0 - ylo;
            bool inpatch = (lx >= 0) && (lx + 1 < PW) && (ly >= 0) && (ly + 1 < PW);

            float w00 = (1.f - fx) * (1.f - fy);
            float w10 = fx * (1.f - fy);
            float w01 = (1.f - fx) * fy;
            float w11 = fx * fy;
            bool vx0 = (ix0 >= 0) && (ix0 < WDIM);
            bool vx1 = (ix0 + 1 >= 0) && (ix0 + 1 < WDIM);
            bool vy0 = (iy0 >= 0) && (iy0 < HDIM);
            bool vy1 = (iy0 + 1 >= 0) && (iy0 + 1 < HDIM);
            w00 = (vx0 && vy0) ? w00 : 0.f;
            w10 = (vx1 && vy0) ? w10 : 0.f;
            w01 = (vx0 && vy1) ? w01 : 0.f;
            w11 = (vx1 && vy1) ? w11 : 0.f;

            if (inpatch) {
                const float* p00 = patch + (ly * PW + lx) * HD + lane;
                float v00 = p00[0];
                float v10 = p00[HD];
                float v01 = p00[PW * HD];
                float v11 = p00[PW * HD + HD];
                acc = fmaf(a, w00 * v00 + w10 * v10 + w01 * v01 + w11 * v11, acc);
            } else {
                int cx0 = min(max(ix0, 0), WDIM - 1);
                int cx1 = min(max(ix0 + 1, 0), WDIM - 1);
                int cy0 = min(max(iy0, 0), HDIM - 1);
                int cy1 = min(max(iy0 + 1, 0), HDIM - 1);
                float v00 = vbase[(size_t)(cy0 * WDIM + cx0) * D];
                float v10 = vbase[(size_t)(cy0 * WDIM + cx1) * D];
                float v01 = vbase[(size_t)(cy1 * WDIM + cx0) * D];
                float v11 = vbase[(size_t)(cy1 * WDIM + cx1) * D];
                acc = fmaf(a, w00 * v00 + w10 * v10 + w01 * v01 + w11 * v11, acc);
            }
        }
        OUT[(size_t)l * D + h * HD + lane] = __float2bfloat16_rn(acc);
    }
}

// ---- fused residual + LayerNorm, float4-vectorized (+opt Qh / bf16 copy) --
template <bool WRITE_Q, bool WRITE_H>
__global__ void ln_residual_kernel(const float* __restrict__ Xin,
                                   const float* __restrict__ Add,
                                   const float* __restrict__ gamma,
                                   const float* __restrict__ beta,
                                   float* __restrict__ Out,
                                   const float* __restrict__ P,
                                   __nv_bfloat16* __restrict__ Qh,
                                   __nv_bfloat16* __restrict__ Hout) {
    int row  = blockIdx.x * (blockDim.x >> 5) + (threadIdx.x >> 5);
    int lane = threadIdx.x & 31;
    if (row >= L) return;
    const size_t base = (size_t)row * D + lane * 8;

    float v[8];
    {
        float4 a0 = *(const float4*)(Xin + base);
        float4 a1 = *(const float4*)(Xin + base + 4);
        float4 b0 = *(const float4*)(Add + base);
        float4 b1 = *(const float4*)(Add + base + 4);
        v[0] = a0.x + b0.x; v[1] = a0.y + b0.y; v[2] = a0.z + b0.z; v[3] = a0.w + b0.w;
        v[4] = a1.x + b1.x; v[5] = a1.y + b1.y; v[6] = a1.z + b1.z; v[7] = a1.w + b1.w;
    }
    float s = 0.f;
#pragma unroll
    for (int i = 0; i < 8; i++) s += v[i];
#pragma unroll
    for (int o = 16; o; o >>= 1) s += __shfl_xor_sync(0xFFFFFFFFu, s, o);
    float m = s * (1.f / D);
    float vs = 0.f;
#pragma unroll
    for (int i = 0; i < 8; i++) { float d = v[i] - m; vs += d * d; }
#pragma unroll
    for (int o = 16; o; o >>= 1) vs += __shfl_xor_sync(0xFFFFFFFFu, vs, o);
    float rstd = rsqrtf(vs * (1.f / D) + EPS);

    float4 g0 = *(const float4*)(gamma + lane * 8);
    float4 g1 = *(const float4*)(gamma + lane * 8 + 4);
    float4 be0 = *(const float4*)(beta + lane * 8);
    float4 be1 = *(const float4*)(beta + lane * 8 + 4);
    float o[8];
    o[0] = (v[0] - m) * rstd * g0.x + be0.x;
    o[1] = (v[1] - m) * rstd * g0.y + be0.y;
    o[2] = (v[2] - m) * rstd * g0.z + be0.z;
    o[3] = (v[3] - m) * rstd * g0.w + be0.w;
    o[4] = (v[4] - m) * rstd * g1.x + be1.x;
    o[5] = (v[5] - m) * rstd * g1.y + be1.y;
    o[6] = (v[6] - m) * rstd * g1.z + be1.z;
    o[7] = (v[7] - m) * rstd * g1.w + be1.w;

    *(float4*)(Out + base)     = make_float4(o[0], o[1], o[2], o[3]);
    *(float4*)(Out + base + 4) = make_float4(o[4], o[5], o[6], o[7]);
    if (WRITE_Q) {
        float4 p0 = *(const float4*)(P + base);
        float4 p1 = *(const float4*)(P + base + 4);
        uint4 q;
        __nv_bfloat162 q0 = __floats2bfloat162_rn(o[0] + p0.x, o[1] + p0.y);
        __nv_bfloat162 q1 = __floats2bfloat162_rn(o[2] + p0.z, o[3] + p0.w);
        __nv_bfloat162 q2 = __floats2bfloat162_rn(o[4] + p1.x, o[5] + p1.y);
        __nv_bfloat162 q3 = __floats2bfloat162_rn(o[6] + p1.z, o[7] + p1.w);
        q.x = *(uint32_t*)&q0; q.y = *(uint32_t*)&q1;
        q.z = *(uint32_t*)&q2; q.w = *(uint32_t*)&q3;
        *(uint4*)(Qh + base) = q;
    }
    if (WRITE_H) {
        uint4 h;
        __nv_bfloat162 h0 = __floats2bfloat162_rn(o[0], o[1]);
        __nv_bfloat162 h1 = __floats2bfloat162_rn(o[2], o[3]);
        __nv_bfloat162 h2 = __floats2bfloat162_rn(o[4], o[5]);
        __nv_bfloat162 h3 = __floats2bfloat162_rn(o[6], o[7]);
        h.x = *(uint32_t*)&h0; h.y = *(uint32_t*)&h1;
        h.z = *(uint32_t*)&h2; h.w = *(uint32_t*)&h3;
        *(uint4*)(Hout + base) = h;
    }
}

// ------------------------- host-side launchers -----------------------------
template <int EPI>
static void launch_hmma_gemm(const __nv_bfloat16* A, const __nv_bfloat16* Bo,
                             const float* bias, void* C, int M, int N, int K) {
    cudaFuncSetAttribute(hmma_gemm_kernel<EPI>,
                         cudaFuncAttributeMaxDynamicSharedMemorySize, HGEMM_SMEM);
    dim3 grid(N / BN, M / BM);
    hmma_gemm_kernel<EPI><<<grid, 256, HGEMM_SMEM>>>(A, Bo, bias, C, M, N, K);
}

extern "C" void kernel_launch(void* const* d_in, const int* in_sizes, int n_in,
                              void* d_out, int out_size) {
    const float* src   = (const float*)d_in[0];
    const float* pos   = (const float*)d_in[1];
    const float* Wv    = (const float*)d_in[2];
    const float* bv    = (const float*)d_in[3];
    const float* Wbox  = (const float*)d_in[4];
    const float* bbox  = (const float*)d_in[5];
    const float* Wattn = (const float*)d_in[6];
    const float* battn = (const float*)d_in[7];
    const float* Wo    = (const float*)d_in[8];
    const float* bo    = (const float*)d_in[9];
    const float* W1    = (const float*)d_in[10];
    const float* b1    = (const float*)d_in[11];
    const float* W2    = (const float*)d_in[12];
    const float* b2    = (const float*)d_in[13];
    const float* ln1_g = (const float*)d_in[14];
    const float* ln1_b = (const float*)d_in[15];
    const float* ln2_g = (const float*)d_in[16];
    const float* ln2_b = (const float*)d_in[17];

    float *X, *P, *VAL, *TMP, *AWOFF, *BCAT;
    __nv_bfloat16 *Qh, *OUTh, *Xh, *FFh, *WCATh, *W1h, *W2h, *Woh, *Wvh;
    cudaGetSymbolAddress((void**)&X,     g_X);
    cudaGetSymbolAddress((void**)&P,     g_P);
    cudaGetSymbolAddress((void**)&VAL,   g_VAL);
    cudaGetSymbolAddress((void**)&TMP,   g_TMP);
    cudaGetSymbolAddress((void**)&AWOFF, g_AWOFF);
    cudaGetSymbolAddress((void**)&BCAT,  g_BCAT);
    cudaGetSymbolAddress((void**)&Qh,    g_Qh);
    cudaGetSymbolAddress((void**)&OUTh,  g_OUTh);
    cudaGetSymbolAddress((void**)&Xh,    g_Xh);
    cudaGetSymbolAddress((void**)&FFh,   g_FFh);
    cudaGetSymbolAddress((void**)&WCATh, g_WCATh);
    cudaGetSymbolAddress((void**)&W1h,   g_W1h);
    cudaGetSymbolAddress((void**)&W2h,   g_W2h);
    cudaGetSymbolAddress((void**)&Woh,   g_Woh);
    cudaGetSymbolAddress((void**)&Wvh,   g_Wvh);

    cudaFuncSetAttribute(box_sample_tiled_kernel,
                         cudaFuncAttributeMaxDynamicSharedMemorySize, SAMP_SMEM);
    cudaFuncSetAttribute(hmma_gemm_dual_kernel,
                         cudaFuncAttributeMaxDynamicSharedMemorySize, HGEMM_SMEM);

    {
        dim3 tb(32, 8);
        dim3 tg(L / 32, D / 32);
        transpose2_kernel<<<tg, tb>>>(src, pos, X, P, Qh, Xh);
    }
    {
        dim3 cg(((D / 8) * DFF + 255) / 256, 8);
        convert_all_kernel<<<cg, 256>>>(W1, W2, Wo, Wv, W1h, W2h, Woh, Wvh);
        dim3 kg(D / 8, 2);
        concat_wb_bf16_kernel<<<kg, NCATP>>>(Wattn, battn, Wbox, bbox, WCATh, BCAT);
    }

    for (int i = 0; i < 2; i++) {
        const float* bv_i    = bv    + (size_t)i * D;
        const float* bo_i    = bo    + (size_t)i * D;
        const float* b1_i    = b1    + (size_t)i * DFF;
        const float* b2_i    = b2    + (size_t)i * D;
        const float* ln1g_i  = ln1_g + (size_t)i * D;
        const float* ln1b_i  = ln1_b + (size_t)i * D;
        const float* ln2g_i  = ln2_g + (size_t)i * D;
        const float* ln2b_i  = ln2_b + (size_t)i * D;

        // fused dual GEMM: VAL = Xh @ Wv + bv  AND  AWOFF = Qh @ WCAT + BCAT
        {
            dim3 grid(D / BN, L / BM, 2);
            hmma_gemm_dual_kernel<<<grid, 256, HGEMM_SMEM>>>(
                Xh, Wvh + (size_t)i * D * D, bv_i, VAL,
                Qh, WCATh + (size_t)i * D * NCATP, BCAT + i * NCATP, AWOFF,
                L, D, D);
        }

        {
            dim3 sg(64, NH);
            box_sample_tiled_kernel<<<sg, 256, SAMP_SMEM>>>(VAL, AWOFF, OUTh);
        }

        launch_hmma_gemm<1>(OUTh, Woh + (size_t)i * D * D, bo_i, TMP, L, D, D);
        ln_residual_kernel<false, true><<<L / 8, 256>>>(X, TMP, ln1g_i, ln1b_i, X,
                                                        nullptr, nullptr, Xh);

        launch_hmma_gemm<2>(Xh, W1h + (size_t)i * D * DFF, b1_i, FFh, L, DFF, D);
        launch_hmma_gemm<1>(FFh, W2h + (size_t)i * DFF * D, b2_i, TMP, L, D, DFF);

        if (i == 0) {
            ln_residual_kernel<true, true><<<L / 8, 256>>>(X, TMP, ln2g_i, ln2b_i, X,
                                                           P, Qh, Xh);
        } else {
            ln_residual_kernel<false, false><<<L / 8, 256>>>(X, TMP, ln2g_i, ln2b_i,
                                                             (float*)d_out,
                                                             nullptr, nullptr, nullptr);
        }
    }
}

// round 15
// speedup vs baseline: 1.0537x; 1.0537x over previous
#include <cuda_runtime.h>
#include <cuda_bf16.h>
#include <cstdint>

// ---------------------------------------------------------------------------
// TransIFF encoder: 2-layer deformable-box-attention transformer encoder.
// B=1, H=W=128 -> L=16384 tokens, D=256, NH=8, HD=32, K2=25, DFF=1024.
// Round 15: R12 config restored (2-stage pipeline, ldmatrix A+B, k-octet
// weights, dual projection GEMM) + bf16 VAL path (halved sampler traffic).
// ---------------------------------------------------------------------------

namespace {
constexpr int L    = 16384;
constexpr int D    = 256;
constexpr int NH   = 8;
constexpr int HD   = 32;
constexpr int K2   = 25;
constexpr int DFF  = 1024;
constexpr int HDIM = 128;
constexpr int WDIM = 128;
constexpr float EPS = 1e-5f;

constexpr int NCAT  = NH * K2 + NH * 4;  // 232 real cols
constexpr int NCATP = 256;               // padded for bf16 GEMM

// ---- bf16 GEMM tiling (R12 proven config) ----
constexpr int BM = 128, BN = 128;
constexpr int HBK   = 64;
constexpr int HASTR = 36;                  // A words/row: 32 data + 4 pad
constexpr int HBSTR = 520;                 // B words/chunk-row: 128 cells*4 + 8 pad
constexpr int HASIZE = BM * HASTR;         // 4608 words
constexpr int HBSIZE = (HBK / 8) * HBSTR;  // 4160 words
constexpr int HSTAGE = HASIZE + HBSIZE;    // 8768 words
constexpr int HGEMM_SMEM = 2 * HSTAGE * 4; // 70144 B

// ---- sampler tiling ----
constexpr int TS   = 16;
constexpr int PAD  = 3;
constexpr int PW   = TS + 2 * PAD;   // 22
constexpr int SAMP_SMEM = PW * PW * HD * 4;          // 61952 B (fp32 patch)
}

// ------------------------- scratch (device globals) -----------------------
__device__ float g_X[L * D];
__device__ float g_P[L * D];
__device__ float g_TMP[L * D];
__device__ float g_AWOFF[L * NCATP];
__device__ float g_BCAT[2 * NCATP];
__device__ __nv_bfloat16 g_VALh[L * D];         // bf16 value projection
__device__ __nv_bfloat16 g_Qh[L * D];
__device__ __nv_bfloat16 g_OUTh[L * D];
__device__ __nv_bfloat16 g_Xh[L * D];
__device__ __nv_bfloat16 g_FFh[L * DFF];
__device__ __nv_bfloat16 g_WCATh[2 * D * NCATP];   // k-octet layout [D/8][NCATP][8]
__device__ __nv_bfloat16 g_W1h[2 * D * DFF];
__device__ __nv_bfloat16 g_W2h[2 * DFF * D];
__device__ __nv_bfloat16 g_Woh[2 * D * D];
__device__ __nv_bfloat16 g_Wvh[2 * D * D];

// ------------------------- PTX helpers ------------------------------------
__device__ __forceinline__ uint32_t smem_u32(const void* p) {
    return (uint32_t)__cvta_generic_to_shared(p);
}
__device__ __forceinline__ void cp_async16(uint32_t saddr, const void* gaddr) {
    asm volatile("cp.async.ca.shared.global [%0], [%1], 16;\n" :: "r"(saddr), "l"(gaddr));
}
__device__ __forceinline__ void cp_commit() { asm volatile("cp.async.commit_group;\n"); }
template <int NG>
__device__ __forceinline__ void cp_wait() { asm volatile("cp.async.wait_group %0;\n" :: "n"(NG)); }

__device__ __forceinline__ void mma_bf16(float d[4], const uint32_t a[4], const uint32_t b[2]) {
    asm volatile(
        "mma.sync.aligned.m16n8k16.row.col.f32.bf16.bf16.f32 "
        "{%0,%1,%2,%3}, {%4,%5,%6,%7}, {%8,%9}, {%0,%1,%2,%3};\n"
        : "+f"(d[0]), "+f"(d[1]), "+f"(d[2]), "+f"(d[3])
        : "r"(a[0]), "r"(a[1]), "r"(a[2]), "r"(a[3]), "r"(b[0]), "r"(b[1]));
}
__device__ __forceinline__ void ldsm_x4(uint32_t r[4], uint32_t saddr) {
    asm volatile("ldmatrix.sync.aligned.m8n8.x4.shared.b16 {%0,%1,%2,%3}, [%4];"
                 : "=r"(r[0]), "=r"(r[1]), "=r"(r[2]), "=r"(r[3]) : "r"(saddr));
}

// ------------------------- bf16 tensor-core GEMM body ----------------------
// C[M,N] = A[M,K] @ B[K,N] (+bias)(+relu). A row-major bf16. Bo: k-octet
// interleaved bf16 [K/8][N][8]. M%128==0, N%128==0, K%64==0.
// EPI: 1 = fp32+bias ; 2 = bf16+bias+relu ; 3 = bf16+bias.
template <int EPI>
__device__ __forceinline__ void
hmma_gemm_body(const __nv_bfloat16* __restrict__ A, const __nv_bfloat16* __restrict__ Bo,
               const float* __restrict__ bias, void* __restrict__ Cout,
               int M, int N, int K, int bm, int bn, uint32_t* smem) {
    const int tid  = threadIdx.x;
    const int warp = tid >> 5;
    const int lane = tid & 31;
    const int g    = lane >> 2;
    const int t    = lane & 3;
    const int wm   = warp & 1;
    const int wn   = warp >> 1;

    auto load_tile = [&](int stage, int k0) {
        uint32_t abase = smem_u32(smem + stage * HSTAGE);
#pragma unroll
        for (int it = 0; it < 4; it++) {
            int id = tid + it * 256;
            int r = id >> 3;
            int c = id & 7;
            cp_async16(abase + (r * HASTR + c * 4) * 4,
                       A + (size_t)(bm + r) * K + k0 + c * 8);
        }
        uint32_t bbase = smem_u32(smem + stage * HSTAGE + HASIZE);
#pragma unroll
        for (int it = 0; it < 4; it++) {
            int id = tid + it * 256;
            int chunk = id >> 7;       // 0..7 (HBK/8)
            int n     = id & 127;      // 0..127
            cp_async16(bbase + (chunk * HBSTR + n * 4) * 4,
                       Bo + ((size_t)(k0 / 8 + chunk) * N + bn + n) * 8);
        }
    };

    // ldmatrix lane address components
    const int lrow  = lane & 15;               // A: row within 16-row frag
    const int koff  = ((lane >> 4) & 1) * 4;   // A: word offset for k+8 half
    const int bnsel = ((lane >> 4) & 1) * 8 + (lane & 7);  // B: col within 16
    const int bcsel = (lane >> 3) & 1;                     // B: chunk 0/1

    float acc[4][4][4] = {};

    const int nk = K / HBK;
    load_tile(0, 0);
    cp_commit();

    for (int kt = 0; kt < nk; kt++) {
        const int cur = kt & 1;
        cp_wait<0>();
        __syncthreads();
        if (kt + 1 < nk) {
            load_tile(cur ^ 1, (kt + 1) * HBK);
            cp_commit();
        }

        const uint32_t* Ac = smem + cur * HSTAGE;
        const uint32_t AcAddr = smem_u32(Ac);
        const uint32_t BcAddr = smem_u32(Ac + HASIZE);
        uint32_t arow[4];
#pragma unroll
        for (int mt = 0; mt < 4; mt++) {
            int row = wm * 64 + mt * 16 + lrow;
            arow[mt] = AcAddr + (row * HASTR + koff) * 4;
        }
        const uint32_t bbase0 = BcAddr + (bcsel * HBSTR + (wn * 32 + bnsel) * 4) * 4;
        const uint32_t bbase1 = bbase0 + 16 * 4 * 4;   // cols +16

#pragma unroll
        for (int k16 = 0; k16 < HBK; k16 += 16) {
            const int kw = k16 >> 1;        // A word offset
            const int kc = k16 >> 3;        // B chunk base (0,2,4,6)
            uint32_t af[4][4], bf0[4], bf1[4];
#pragma unroll
            for (int mt = 0; mt < 4; mt++)
                ldsm_x4(af[mt], arow[mt] + kw * 4);
            ldsm_x4(bf0, bbase0 + kc * HBSTR * 4);   // nt 0,1
            ldsm_x4(bf1, bbase1 + kc * HBSTR * 4);   // nt 2,3
            uint32_t bf[4][2] = {{bf0[0], bf0[1]}, {bf0[2], bf0[3]},
                                 {bf1[0], bf1[1]}, {bf1[2], bf1[3]}};
#pragma unroll
            for (int mt = 0; mt < 4; mt++)
#pragma unroll
                for (int nt = 0; nt < 4; nt++)
                    mma_bf16(acc[mt][nt], af[mt], bf[nt]);
        }
    }

#pragma unroll
    for (int mt = 0; mt < 4; mt++) {
        int r0 = bm + wm * 64 + mt * 16 + g;
#pragma unroll
        for (int nt = 0; nt < 4; nt++) {
            int col = bn + wn * 32 + nt * 8 + 2 * t;
            float b0 = bias[col], b1 = bias[col + 1];
            float v0 = acc[mt][nt][0] + b0;
            float v1 = acc[mt][nt][1] + b1;
            float v2 = acc[mt][nt][2] + b0;
            float v3 = acc[mt][nt][3] + b1;
            if (EPI == 2) {
                v0 = fmaxf(v0, 0.f); v1 = fmaxf(v1, 0.f);
                v2 = fmaxf(v2, 0.f); v3 = fmaxf(v3, 0.f);
            }
            if (EPI >= 2) {
                __nv_bfloat16* C = (__nv_bfloat16*)Cout;
                *(__nv_bfloat162*)(C + (size_t)r0 * N + col)       = __floats2bfloat162_rn(v0, v1);
                *(__nv_bfloat162*)(C + (size_t)(r0 + 8) * N + col) = __floats2bfloat162_rn(v2, v3);
            } else {
                float* C = (float*)Cout;
                *(float2*)(C + (size_t)r0 * N + col)       = make_float2(v0, v1);
                *(float2*)(C + (size_t)(r0 + 8) * N + col) = make_float2(v2, v3);
            }
        }
    }
}

template <int EPI>
__global__ void __launch_bounds__(256, 2)
hmma_gemm_kernel(const __nv_bfloat16* __restrict__ A, const __nv_bfloat16* __restrict__ Bo,
                 const float* __restrict__ bias, void* __restrict__ Cout,
                 int M, int N, int K) {
    extern __shared__ uint32_t smem[];
    hmma_gemm_body<EPI>(A, Bo, bias, Cout, M, N, K,
                        blockIdx.y * BM, blockIdx.x * BN, smem);
}

// Dual GEMM: blockIdx.z selects problem. Problem 0 (VAL) writes bf16 (EPI=3),
// problem 1 (AWOFF) writes fp32 (EPI=1).
__global__ void __launch_bounds__(256, 2)
hmma_gemm_dual_kernel(const __nv_bfloat16* __restrict__ A0, const __nv_bfloat16* __restrict__ B0,
                      const float* __restrict__ bias0, void* __restrict__ C0,
                      const __nv_bfloat16* __restrict__ A1, const __nv_bfloat16* __restrict__ B1,
                      const float* __restrict__ bias1, void* __restrict__ C1,
                      int M, int N, int K) {
    extern __shared__ uint32_t smem[];
    if (blockIdx.z == 0)
        hmma_gemm_body<3>(A0, B0, bias0, C0, M, N, K,
                          blockIdx.y * BM, blockIdx.x * BN, smem);
    else
        hmma_gemm_body<1>(A1, B1, bias1, C1, M, N, K,
                          blockIdx.y * BM, blockIdx.x * BN, smem);
}

// ------ all-weights convert: fp32 -> bf16 k-octet interleaved, 1 launch ----
// seg: 0,1 = W1 (K=D,N=DFF); 2,3 = W2 (K=DFF,N=D); 4,5 = Wo; 6,7 = Wv.
__global__ void convert_all_kernel(const float* __restrict__ W1, const float* __restrict__ W2,
                                   const float* __restrict__ Wo, const float* __restrict__ Wv,
                                   __nv_bfloat16* __restrict__ W1h,
                                   __nv_bfloat16* __restrict__ W2h,
                                   __nv_bfloat16* __restrict__ Woh,
                                   __nv_bfloat16* __restrict__ Wvh) {
    int seg = blockIdx.y;
    int Kdim, Ndim;
    const float* W;
    __nv_bfloat16* Wh;
    if (seg < 2)      { Kdim = D;   Ndim = DFF; W = W1 + (size_t)seg * D * DFF;       Wh = W1h + (size_t)seg * D * DFF; }
    else if (seg < 4) { Kdim = DFF; Ndim = D;   W = W2 + (size_t)(seg - 2) * DFF * D; Wh = W2h + (size_t)(seg - 2) * DFF * D; }
    else if (seg < 6) { Kdim = D;   Ndim = D;   W = Wo + (size_t)(seg - 4) * D * D;   Wh = Woh + (size_t)(seg - 4) * D * D; }
    else              { Kdim = D;   Ndim = D;   W = Wv + (size_t)(seg - 6) * D * D;   Wh = Wvh + (size_t)(seg - 6) * D * D; }
    int i = blockIdx.x * blockDim.x + threadIdx.x;
    int total = (Kdim / 8) * Ndim;
    if (i >= total) return;
    int chunk = i / Ndim, n = i % Ndim;
    __nv_bfloat162 o[4];
#pragma unroll
    for (int j = 0; j < 4; j++) {
        float a = W[(size_t)(chunk * 8 + 2 * j)     * Ndim + n];
        float b = W[(size_t)(chunk * 8 + 2 * j + 1) * Ndim + n];
        o[j] = __floats2bfloat162_rn(a, b);
    }
    uint4 v;
    v.x = *(uint32_t*)&o[0]; v.y = *(uint32_t*)&o[1];
    v.z = *(uint32_t*)&o[2]; v.w = *(uint32_t*)&o[3];
    *(uint4*)(Wh + (size_t)i * 8) = v;
}

// ------ merged attn+box weights -> bf16 k-octet, padded to 256, 2 layers ---
__global__ void concat_wb_bf16_kernel(const float* __restrict__ Wattn, const float* __restrict__ battn,
                                      const float* __restrict__ Wbox,  const float* __restrict__ bbox,
                                      __nv_bfloat16* __restrict__ WCh, float* __restrict__ BC) {
    int chunk = blockIdx.x;
    int li    = blockIdx.y;
    int n     = threadIdx.x;
    const float* Wa = Wattn + (size_t)li * D * (NH * K2);
    const float* Wb = Wbox  + (size_t)li * D * (NH * 4);
    __nv_bfloat162 o[4];
#pragma unroll
    for (int j = 0; j < 4; j++) {
        float a = 0.f, b = 0.f;
        int k0 = chunk * 8 + 2 * j;
        if (n < NH * K2) {
            a = Wa[(size_t)k0 * (NH * K2) + n];
            b = Wa[(size_t)(k0 + 1) * (NH * K2) + n];
        } else if (n < NCAT) {
            a = Wb[(size_t)k0 * (NH * 4) + (n - NH * K2)];
            b = Wb[(size_t)(k0 + 1) * (NH * 4) + (n - NH * K2)];
        }
        o[j] = __floats2bfloat162_rn(a, b);
    }
    uint4 v;
    v.x = *(uint32_t*)&o[0]; v.y = *(uint32_t*)&o[1];
    v.z = *(uint32_t*)&o[2]; v.w = *(uint32_t*)&o[3];
    *(uint4*)(WCh + ((size_t)li * (D / 8) * NCATP + (size_t)chunk * NCATP + n) * 8) = v;
    if (chunk == 0) {
        const float* ba = battn + (size_t)li * (NH * K2);
        const float* bb = bbox  + (size_t)li * (NH * 4);
        BC[li * NCATP + n] = (n < NH * K2) ? ba[n] : (n < NCAT ? bb[n - NH * K2] : 0.f);
    }
}

// --- fused transpose: (D,L)x2 -> X, P, Qh=bf16(X+P), Xh=bf16(X) (L,D) ------
__global__ void transpose2_kernel(const float* __restrict__ S, const float* __restrict__ Pp,
                                  float* __restrict__ X, float* __restrict__ P,
                                  __nv_bfloat16* __restrict__ Qh,
                                  __nv_bfloat16* __restrict__ Xh) {
    __shared__ float ts[32][33];
    __shared__ float tp[32][33];
    int bx = blockIdx.x * 32;
    int by = blockIdx.y * 32;
    int tx = threadIdx.x, ty = threadIdx.y;
#pragma unroll
    for (int j = 0; j < 32; j += 8) {
        ts[ty + j][tx] = S [(size_t)(by + ty + j) * L + bx + tx];
        tp[ty + j][tx] = Pp[(size_t)(by + ty + j) * L + bx + tx];
    }
    __syncthreads();
#pragma unroll
    for (int j = 0; j < 32; j += 8) {
        size_t o = (size_t)(bx + ty + j) * D + by + tx;
        float xs = ts[tx][ty + j];
        float ps = tp[tx][ty + j];
        X[o] = xs;
        P[o] = ps;
        Qh[o] = __float2bfloat16_rn(xs + ps);
        Xh[o] = __float2bfloat16_rn(xs);
    }
}

// ------------- smem-tiled deformable box sampling + fused softmax ----------
// VAL is bf16; patch is staged to fp32 smem (inner loop unchanged).
__global__ void __launch_bounds__(256, 3)
box_sample_tiled_kernel(const __nv_bfloat16* __restrict__ VAL,
                        const float* __restrict__ AWOFF,
                        __nv_bfloat16* __restrict__ OUT) {
    extern __shared__ float patch[];   // [PW*PW][32] fp32

    const int tile = blockIdx.x;
    const int h    = blockIdx.y;
    const int tx0  = (tile & 7) * TS;
    const int ty0  = (tile >> 3) * TS;
    const int xlo  = tx0 - PAD;
    const int ylo  = ty0 - PAD;
    const int tid  = threadIdx.x;
    const int warp = tid >> 5;
    const int lane = tid & 31;

    // stage: PW*PW pixels x 32 ch; 8 bf16 per thread-iter (uint4)
    for (int i = tid; i < PW * PW * (HD / 8); i += 256) {
        int pix = i >> 2;
        int c8  = (i & 3) * 8;
        int py  = pix / PW, px = pix % PW;
        int gy  = min(max(ylo + py, 0), HDIM - 1);
        int gx  = min(max(xlo + px, 0), WDIM - 1);
        uint4 v = *(const uint4*)(VAL + (size_t)(gy * WDIM + gx) * D + h * HD + c8);
        float* dst = patch + pix * HD + c8;
        __nv_bfloat162 p0 = *(__nv_bfloat162*)&v.x;
        __nv_bfloat162 p1 = *(__nv_bfloat162*)&v.y;
        __nv_bfloat162 p2 = *(__nv_bfloat162*)&v.z;
        __nv_bfloat162 p3 = *(__nv_bfloat162*)&v.w;
        float2 f0 = __bfloat1622float2(p0);
        float2 f1 = __bfloat1622float2(p1);
        float2 f2 = __bfloat1622float2(p2);
        float2 f3 = __bfloat1622float2(p3);
        *(float4*)(dst)     = make_float4(f0.x, f0.y, f1.x, f1.y);
        *(float4*)(dst + 4) = make_float4(f2.x, f2.y, f3.x, f3.y);
    }
    __syncthreads();

    const __nv_bfloat16* vbase = VAL + h * HD + lane;
    const float scl = 0.025f * 0.125f;

    for (int it = 0; it < 32; it++) {
        int tt = warp * 32 + it;
        int r = tt >> 4, c = tt & 15;
        int gx = tx0 + c, gy = ty0 + r;
        int l = gy * WDIM + gx;

        const float* awl = AWOFF + (size_t)l * NCATP + h * K2;
        float lg = (lane < K2) ? awl[lane] : -1e30f;
        float mx = lg;
#pragma unroll
        for (int o = 16; o; o >>= 1) mx = fmaxf(mx, __shfl_xor_sync(0xFFFFFFFFu, mx, o));
        float e = (lane < K2) ? __expf(lg - mx) : 0.f;
        float s = e;
#pragma unroll
        for (int o = 16; o; o >>= 1) s += __shfl_xor_sync(0xFFFFFFFFu, s, o);
        float wsm = e / s;

        const float* off = AWOFF + (size_t)l * NCATP + NH * K2 + h * 4;
        float bx = (gx + 0.5f) * (1.f / WDIM) + off[0] * scl;
        float by = (gy + 0.5f) * (1.f / HDIM) + off[1] * scl;
        float bw = 0.025f + off[2] * scl;
        float bh = 0.025f + off[3] * scl;

        float acc = 0.f;
#pragma unroll
        for (int k = 0; k < K2; k++) {
            float a = __shfl_sync(0xFFFFFFFFu, wsm, k);
            float gxk = -0.5f + 0.25f * (k % 5);
            float gyk = -0.5f + 0.25f * (k / 5);
            float px = (bx + bw * gxk) * (float)WDIM - 0.5f;
            float py = (by + bh * gyk) * (float)HDIM - 0.5f;
            int ix0 = (int)floorf(px);
            int iy0 = (int)floorf(py);
            float fx = px - (float)ix0;
            float fy = py - (float)iy0;

            int lx = ix0 - xlo, ly = iy0 - ylo;
            bool inpatch = (lx >= 0) && (lx + 1 < PW) && (ly >= 0) && (ly + 1 < PW);

            float w00 = (1.f - fx) * (1.f - fy);
            float w10 = fx * (1.f - fy);
            float w01 = (1.f - fx) * fy;
            float w11 = fx * fy;
            bool vx0 = (ix0 >= 0) && (ix0 < WDIM);
            bool vx1 = (ix0 + 1 >= 0) && (ix0 + 1 < WDIM);
            bool vy0 = (iy0 >= 0) && (iy0 < HDIM);
            bool vy1 = (iy0 + 1 >= 0) && (iy0 + 1 < HDIM);
            w00 = (vx0 && vy0) ? w00 : 0.f;
            w10 = (vx1 && vy0) ? w10 : 0.f;
            w01 = (vx0 && vy1) ? w01 : 0.f;
            w11 = (vx1 && vy1) ? w11 : 0.f;

            if (inpatch) {
                const float* p00 = patch + (ly * PW + lx) * HD + lane;
                float v00 = p00[0];
                float v10 = p00[HD];
                float v01 = p00[PW * HD];
                float v11 = p00[PW * HD + HD];
                acc = fmaf(a, w00 * v00 + w10 * v10 + w01 * v01 + w11 * v11, acc);
            } else {
                int cx0 = min(max(ix0, 0), WDIM - 1);
                int cx1 = min(max(ix0 + 1, 0), WDIM - 1);
                int cy0 = min(max(iy0, 0), HDIM - 1);
                int cy1 = min(max(iy0 + 1, 0), HDIM - 1);
                float v00 = __bfloat162float(vbase[(size_t)(cy0 * WDIM + cx0) * D]);
                float v10 = __bfloat162float(vbase[(size_t)(cy0 * WDIM + cx1) * D]);
                float v01 = __bfloat162float(vbase[(size_t)(cy1 * WDIM + cx0) * D]);
                float v11 = __bfloat162float(vbase[(size_t)(cy1 * WDIM + cx1) * D]);
                acc = fmaf(a, w00 * v00 + w10 * v10 + w01 * v01 + w11 * v11, acc);
            }
        }
        OUT[(size_t)l * D + h * HD + lane] = __float2bfloat16_rn(acc);
    }
}

// ---- fused residual + LayerNorm, float4-vectorized (+opt Qh / bf16 copy) --
template <bool WRITE_Q, bool WRITE_H>
__global__ void ln_residual_kernel(const float* __restrict__ Xin,
                                   const float* __restrict__ Add,
                                   const float* __restrict__ gamma,
                                   const float* __restrict__ beta,
                                   float* __restrict__ Out,
                                   const float* __restrict__ P,
                                   __nv_bfloat16* __restrict__ Qh,
                                   __nv_bfloat16* __restrict__ Hout) {
    int row  = blockIdx.x * (blockDim.x >> 5) + (threadIdx.x >> 5);
    int lane = threadIdx.x & 31;
    if (row >= L) return;
    const size_t base = (size_t)row * D + lane * 8;

    float v[8];
    {
        float4 a0 = *(const float4*)(Xin + base);
        float4 a1 = *(const float4*)(Xin + base + 4);
        float4 b0 = *(const float4*)(Add + base);
        float4 b1 = *(const float4*)(Add + base + 4);
        v[0] = a0.x + b0.x; v[1] = a0.y + b0.y; v[2] = a0.z + b0.z; v[3] = a0.w + b0.w;
        v[4] = a1.x + b1.x; v[5] = a1.y + b1.y; v[6] = a1.z + b1.z; v[7] = a1.w + b1.w;
    }
    float s = 0.f;
#pragma unroll
    for (int i = 0; i < 8; i++) s += v[i];
#pragma unroll
    for (int o = 16; o; o >>= 1) s += __shfl_xor_sync(0xFFFFFFFFu, s, o);
    float m = s * (1.f / D);
    float vs = 0.f;
#pragma unroll
    for (int i = 0; i < 8; i++) { float d = v[i] - m; vs += d * d; }
#pragma unroll
    for (int o = 16; o; o >>= 1) vs += __shfl_xor_sync(0xFFFFFFFFu, vs, o);
    float rstd = rsqrtf(vs * (1.f / D) + EPS);

    float4 g0 = *(const float4*)(gamma + lane * 8);
    float4 g1 = *(const float4*)(gamma + lane * 8 + 4);
    float4 be0 = *(const float4*)(beta + lane * 8);
    float4 be1 = *(const float4*)(beta + lane * 8 + 4);
    float o[8];
    o[0] = (v[0] - m) * rstd * g0.x + be0.x;
    o[1] = (v[1] - m) * rstd * g0.y + be0.y;
    o[2] = (v[2] - m) * rstd * g0.z + be0.z;
    o[3] = (v[3] - m) * rstd * g0.w + be0.w;
    o[4] = (v[4] - m) * rstd * g1.x + be1.x;
    o[5] = (v[5] - m) * rstd * g1.y + be1.y;
    o[6] = (v[6] - m) * rstd * g1.z + be1.z;
    o[7] = (v[7] - m) * rstd * g1.w + be1.w;

    *(float4*)(Out + base)     = make_float4(o[0], o[1], o[2], o[3]);
    *(float4*)(Out + base + 4) = make_float4(o[4], o[5], o[6], o[7]);
    if (WRITE_Q) {
        float4 p0 = *(const float4*)(P + base);
        float4 p1 = *(const float4*)(P + base + 4);
        uint4 q;
        __nv_bfloat162 q0 = __floats2bfloat162_rn(o[0] + p0.x, o[1] + p0.y);
        __nv_bfloat162 q1 = __floats2bfloat162_rn(o[2] + p0.z, o[3] + p0.w);
        __nv_bfloat162 q2 = __floats2bfloat162_rn(o[4] + p1.x, o[5] + p1.y);
        __nv_bfloat162 q3 = __floats2bfloat162_rn(o[6] + p1.z, o[7] + p1.w);
        q.x = *(uint32_t*)&q0; q.y = *(uint32_t*)&q1;
        q.z = *(uint32_t*)&q2; q.w = *(uint32_t*)&q3;
        *(uint4*)(Qh + base) = q;
    }
    if (WRITE_H) {
        uint4 h;
        __nv_bfloat162 h0 = __floats2bfloat162_rn(o[0], o[1]);
        __nv_bfloat162 h1 = __floats2bfloat162_rn(o[2], o[3]);
        __nv_bfloat162 h2 = __floats2bfloat162_rn(o[4], o[5]);
        __nv_bfloat162 h3 = __floats2bfloat162_rn(o[6], o[7]);
        h.x = *(uint32_t*)&h0; h.y = *(uint32_t*)&h1;
        h.z = *(uint32_t*)&h2; h.w = *(uint32_t*)&h3;
        *(uint4*)(Hout + base) = h;
    }
}

// ------------------------- host-side launchers -----------------------------
template <int EPI>
static void launch_hmma_gemm(const __nv_bfloat16* A, const __nv_bfloat16* Bo,
                             const float* bias, void* C, int M, int N, int K) {
    cudaFuncSetAttribute(hmma_gemm_kernel<EPI>,
                         cudaFuncAttributeMaxDynamicSharedMemorySize, HGEMM_SMEM);
    dim3 grid(N / BN, M / BM);
    hmma_gemm_kernel<EPI><<<grid, 256, HGEMM_SMEM>>>(A, Bo, bias, C, M, N, K);
}

extern "C" void kernel_launch(void* const* d_in, const int* in_sizes, int n_in,
                              void* d_out, int out_size) {
    const float* src   = (const float*)d_in[0];
    const float* pos   = (const float*)d_in[1];
    const float* Wv    = (const float*)d_in[2];
    const float* bv    = (const float*)d_in[3];
    const float* Wbox  = (const float*)d_in[4];
    const float* bbox  = (const float*)d_in[5];
    const float* Wattn = (const float*)d_in[6];
    const float* battn = (const float*)d_in[7];
    const float* Wo    = (const float*)d_in[8];
    const float* bo    = (const float*)d_in[9];
    const float* W1    = (const float*)d_in[10];
    const float* b1    = (const float*)d_in[11];
    const float* W2    = (const float*)d_in[12];
    const float* b2    = (const float*)d_in[13];
    const float* ln1_g = (const float*)d_in[14];
    const float* ln1_b = (const float*)d_in[15];
    const float* ln2_g = (const float*)d_in[16];
    const float* ln2_b = (const float*)d_in[17];

    float *X, *P, *TMP, *AWOFF, *BCAT;
    __nv_bfloat16 *VALh, *Qh, *OUTh, *Xh, *FFh, *WCATh, *W1h, *W2h, *Woh, *Wvh;
    cudaGetSymbolAddress((void**)&X,     g_X);
    cudaGetSymbolAddress((void**)&P,     g_P);
    cudaGetSymbolAddress((void**)&TMP,   g_TMP);
    cudaGetSymbolAddress((void**)&AWOFF, g_AWOFF);
    cudaGetSymbolAddress((void**)&BCAT,  g_BCAT);
    cudaGetSymbolAddress((void**)&VALh,  g_VALh);
    cudaGetSymbolAddress((void**)&Qh,    g_Qh);
    cudaGetSymbolAddress((void**)&OUTh,  g_OUTh);
    cudaGetSymbolAddress((void**)&Xh,    g_Xh);
    cudaGetSymbolAddress((void**)&FFh,   g_FFh);
    cudaGetSymbolAddress((void**)&WCATh, g_WCATh);
    cudaGetSymbolAddress((void**)&W1h,   g_W1h);
    cudaGetSymbolAddress((void**)&W2h,   g_W2h);
    cudaGetSymbolAddress((void**)&Woh,   g_Woh);
    cudaGetSymbolAddress((void**)&Wvh,   g_Wvh);

    cudaFuncSetAttribute(box_sample_tiled_kernel,
                         cudaFuncAttributeMaxDynamicSharedMemorySize, SAMP_SMEM);
    cudaFuncSetAttribute(hmma_gemm_dual_kernel,
                         cudaFuncAttributeMaxDynamicSharedMemorySize, HGEMM_SMEM);

    {
        dim3 tb(32, 8);
        dim3 tg(L / 32, D / 32);
        transpose2_kernel<<<tg, tb>>>(src, pos, X, P, Qh, Xh);
    }
    {
        dim3 cg(((D / 8) * DFF + 255) / 256, 8);
        convert_all_kernel<<<cg, 256>>>(W1, W2, Wo, Wv, W1h, W2h, Woh, Wvh);
        dim3 kg(D / 8, 2);
        concat_wb_bf16_kernel<<<kg, NCATP>>>(Wattn, battn, Wbox, bbox, WCATh, BCAT);
    }

    for (int i = 0; i < 2; i++) {
        const float* bv_i    = bv    + (size_t)i * D;
        const float* bo_i    = bo    + (size_t)i * D;
        const float* b1_i    = b1    + (size_t)i * DFF;
        const float* b2_i    = b2    + (size_t)i * D;
        const float* ln1g_i  = ln1_g + (size_t)i * D;
        const float* ln1b_i  = ln1_b + (size_t)i * D;
        const float* ln2g_i  = ln2_g + (size_t)i * D;
        const float* ln2b_i  = ln2_b + (size_t)i * D;

        // fused dual GEMM: VALh = bf16(Xh @ Wv + bv) ; AWOFF = Qh @ WCAT + BCAT
        {
            dim3 grid(D / BN, L / BM, 2);
            hmma_gemm_dual_kernel<<<grid, 256, HGEMM_SMEM>>>(
                Xh, Wvh + (size_t)i * D * D, bv_i, VALh,
                Qh, WCATh + (size_t)i * D * NCATP, BCAT + i * NCATP, AWOFF,
                L, D, D);
        }

        {
            dim3 sg(64, NH);
            box_sample_tiled_kernel<<<sg, 256, SAMP_SMEM>>>(VALh, AWOFF, OUTh);
        }

        launch_hmma_gemm<1>(OUTh, Woh + (size_t)i * D * D, bo_i, TMP, L, D, D);
        ln_residual_kernel<false, true><<<L / 8, 256>>>(X, TMP, ln1g_i, ln1b_i, X,
                                                        nullptr, nullptr, Xh);

        launch_hmma_gemm<2>(Xh, W1h + (size_t)i * D * DFF, b1_i, FFh, L, DFF, D);
        launch_hmma_gemm<1>(FFh, W2h + (size_t)i * DFF * D, b2_i, TMP, L, D, DFF);

        if (i == 0) {
            ln_residual_kernel<true, true><<<L / 8, 256>>>(X, TMP, ln2g_i, ln2b_i, X,
                                                           P, Qh, Xh);
        } else {
            ln_residual_kernel<false, false><<<L / 8, 256>>>(X, TMP, ln2g_i, ln2b_i,
                                                             (float*)d_out,
                                                             nullptr, nullptr, nullptr);
        }
    }
}

// round 16
// speedup vs baseline: 1.0539x; 1.0002x over previous
#include <cuda_runtime.h>
#include <cuda_bf16.h>
#include <cstdint>

// ---------------------------------------------------------------------------
// TransIFF encoder: 2-layer deformable-box-attention transformer encoder.
// B=1, H=W=128 -> L=16384 tokens, D=256, NH=8, HD=32, K2=25, DFF=1024.
// Round 16: R15 + bf16 TMP path (Wo/W2 outputs bf16; LN residual-add reads
// bf16). fp32 kept only on the X residual chain and attention logits.
// ---------------------------------------------------------------------------

namespace {
constexpr int L    = 16384;
constexpr int D    = 256;
constexpr int NH   = 8;
constexpr int HD   = 32;
constexpr int K2   = 25;
constexpr int DFF  = 1024;
constexpr int HDIM = 128;
constexpr int WDIM = 128;
constexpr float EPS = 1e-5f;

constexpr int NCAT  = NH * K2 + NH * 4;  // 232 real cols
constexpr int NCATP = 256;               // padded for bf16 GEMM

// ---- bf16 GEMM tiling (R12 proven config) ----
constexpr int BM = 128, BN = 128;
constexpr int HBK   = 64;
constexpr int HASTR = 36;                  // A words/row: 32 data + 4 pad
constexpr int HBSTR = 520;                 // B words/chunk-row: 128 cells*4 + 8 pad
constexpr int HASIZE = BM * HASTR;         // 4608 words
constexpr int HBSIZE = (HBK / 8) * HBSTR;  // 4160 words
constexpr int HSTAGE = HASIZE + HBSIZE;    // 8768 words
constexpr int HGEMM_SMEM = 2 * HSTAGE * 4; // 70144 B

// ---- sampler tiling ----
constexpr int TS   = 16;
constexpr int PAD  = 3;
constexpr int PW   = TS + 2 * PAD;   // 22
constexpr int SAMP_SMEM = PW * PW * HD * 4;          // 61952 B (fp32 patch)
}

// ------------------------- scratch (device globals) -----------------------
__device__ float g_X[L * D];
__device__ float g_P[L * D];
__device__ float g_AWOFF[L * NCATP];
__device__ float g_BCAT[2 * NCATP];
__device__ __nv_bfloat16 g_TMPh[L * D];         // bf16 GEMM residual deltas
__device__ __nv_bfloat16 g_VALh[L * D];         // bf16 value projection
__device__ __nv_bfloat16 g_Qh[L * D];
__device__ __nv_bfloat16 g_OUTh[L * D];
__device__ __nv_bfloat16 g_Xh[L * D];
__device__ __nv_bfloat16 g_FFh[L * DFF];
__device__ __nv_bfloat16 g_WCATh[2 * D * NCATP];   // k-octet layout
__device__ __nv_bfloat16 g_W1h[2 * D * DFF];
__device__ __nv_bfloat16 g_W2h[2 * DFF * D];
__device__ __nv_bfloat16 g_Woh[2 * D * D];
__device__ __nv_bfloat16 g_Wvh[2 * D * D];

// ------------------------- PTX helpers ------------------------------------
__device__ __forceinline__ uint32_t smem_u32(const void* p) {
    return (uint32_t)__cvta_generic_to_shared(p);
}
__device__ __forceinline__ void cp_async16(uint32_t saddr, const void* gaddr) {
    asm volatile("cp.async.ca.shared.global [%0], [%1], 16;\n" :: "r"(saddr), "l"(gaddr));
}
__device__ __forceinline__ void cp_commit() { asm volatile("cp.async.commit_group;\n"); }
template <int NG>
__device__ __forceinline__ void cp_wait() { asm volatile("cp.async.wait_group %0;\n" :: "n"(NG)); }

__device__ __forceinline__ void mma_bf16(float d[4], const uint32_t a[4], const uint32_t b[2]) {
    asm volatile(
        "mma.sync.aligned.m16n8k16.row.col.f32.bf16.bf16.f32 "
        "{%0,%1,%2,%3}, {%4,%5,%6,%7}, {%8,%9}, {%0,%1,%2,%3};\n"
        : "+f"(d[0]), "+f"(d[1]), "+f"(d[2]), "+f"(d[3])
        : "r"(a[0]), "r"(a[1]), "r"(a[2]), "r"(a[3]), "r"(b[0]), "r"(b[1]));
}
__device__ __forceinline__ void ldsm_x4(uint32_t r[4], uint32_t saddr) {
    asm volatile("ldmatrix.sync.aligned.m8n8.x4.shared.b16 {%0,%1,%2,%3}, [%4];"
                 : "=r"(r[0]), "=r"(r[1]), "=r"(r[2]), "=r"(r[3]) : "r"(saddr));
}

// ------------------------- bf16 tensor-core GEMM body ----------------------
// C[M,N] = A[M,K] @ B[K,N] (+bias)(+relu). A row-major bf16. Bo: k-octet
// interleaved bf16 [K/8][N][8]. M%128==0, N%128==0, K%64==0.
// EPI: 1 = fp32+bias ; 2 = bf16+bias+relu ; 3 = bf16+bias.
template <int EPI>
__device__ __forceinline__ void
hmma_gemm_body(const __nv_bfloat16* __restrict__ A, const __nv_bfloat16* __restrict__ Bo,
               const float* __restrict__ bias, void* __restrict__ Cout,
               int M, int N, int K, int bm, int bn, uint32_t* smem) {
    const int tid  = threadIdx.x;
    const int warp = tid >> 5;
    const int lane = tid & 31;
    const int g    = lane >> 2;
    const int t    = lane & 3;
    const int wm   = warp & 1;
    const int wn   = warp >> 1;

    auto load_tile = [&](int stage, int k0) {
        uint32_t abase = smem_u32(smem + stage * HSTAGE);
#pragma unroll
        for (int it = 0; it < 4; it++) {
            int id = tid + it * 256;
            int r = id >> 3;
            int c = id & 7;
            cp_async16(abase + (r * HASTR + c * 4) * 4,
                       A + (size_t)(bm + r) * K + k0 + c * 8);
        }
        uint32_t bbase = smem_u32(smem + stage * HSTAGE + HASIZE);
#pragma unroll
        for (int it = 0; it < 4; it++) {
            int id = tid + it * 256;
            int chunk = id >> 7;       // 0..7 (HBK/8)
            int n     = id & 127;      // 0..127
            cp_async16(bbase + (chunk * HBSTR + n * 4) * 4,
                       Bo + ((size_t)(k0 / 8 + chunk) * N + bn + n) * 8);
        }
    };

    const int lrow  = lane & 15;
    const int koff  = ((lane >> 4) & 1) * 4;
    const int bnsel = ((lane >> 4) & 1) * 8 + (lane & 7);
    const int bcsel = (lane >> 3) & 1;

    float acc[4][4][4] = {};

    const int nk = K / HBK;
    load_tile(0, 0);
    cp_commit();

    for (int kt = 0; kt < nk; kt++) {
        const int cur = kt & 1;
        cp_wait<0>();
        __syncthreads();
        if (kt + 1 < nk) {
            load_tile(cur ^ 1, (kt + 1) * HBK);
            cp_commit();
        }

        const uint32_t* Ac = smem + cur * HSTAGE;
        const uint32_t AcAddr = smem_u32(Ac);
        const uint32_t BcAddr = smem_u32(Ac + HASIZE);
        uint32_t arow[4];
#pragma unroll
        for (int mt = 0; mt < 4; mt++) {
            int row = wm * 64 + mt * 16 + lrow;
            arow[mt] = AcAddr + (row * HASTR + koff) * 4;
        }
        const uint32_t bbase0 = BcAddr + (bcsel * HBSTR + (wn * 32 + bnsel) * 4) * 4;
        const uint32_t bbase1 = bbase0 + 16 * 4 * 4;

#pragma unroll
        for (int k16 = 0; k16 < HBK; k16 += 16) {
            const int kw = k16 >> 1;
            const int kc = k16 >> 3;
            uint32_t af[4][4], bf0[4], bf1[4];
#pragma unroll
            for (int mt = 0; mt < 4; mt++)
                ldsm_x4(af[mt], arow[mt] + kw * 4);
            ldsm_x4(bf0, bbase0 + kc * HBSTR * 4);
            ldsm_x4(bf1, bbase1 + kc * HBSTR * 4);
            uint32_t bf[4][2] = {{bf0[0], bf0[1]}, {bf0[2], bf0[3]},
                                 {bf1[0], bf1[1]}, {bf1[2], bf1[3]}};
#pragma unroll
            for (int mt = 0; mt < 4; mt++)
#pragma unroll
                for (int nt = 0; nt < 4; nt++)
                    mma_bf16(acc[mt][nt], af[mt], bf[nt]);
        }
    }

#pragma unroll
    for (int mt = 0; mt < 4; mt++) {
        int r0 = bm + wm * 64 + mt * 16 + g;
#pragma unroll
        for (int nt = 0; nt < 4; nt++) {
            int col = bn + wn * 32 + nt * 8 + 2 * t;
            float b0 = bias[col], b1 = bias[col + 1];
            float v0 = acc[mt][nt][0] + b0;
            float v1 = acc[mt][nt][1] + b1;
            float v2 = acc[mt][nt][2] + b0;
            float v3 = acc[mt][nt][3] + b1;
            if (EPI == 2) {
                v0 = fmaxf(v0, 0.f); v1 = fmaxf(v1, 0.f);
                v2 = fmaxf(v2, 0.f); v3 = fmaxf(v3, 0.f);
            }
            if (EPI >= 2) {
                __nv_bfloat16* C = (__nv_bfloat16*)Cout;
                *(__nv_bfloat162*)(C + (size_t)r0 * N + col)       = __floats2bfloat162_rn(v0, v1);
                *(__nv_bfloat162*)(C + (size_t)(r0 + 8) * N + col) = __floats2bfloat162_rn(v2, v3);
            } else {
                float* C = (float*)Cout;
                *(float2*)(C + (size_t)r0 * N + col)       = make_float2(v0, v1);
                *(float2*)(C + (size_t)(r0 + 8) * N + col) = make_float2(v2, v3);
            }
        }
    }
}

template <int EPI>
__global__ void __launch_bounds__(256, 2)
hmma_gemm_kernel(const __nv_bfloat16* __restrict__ A, const __nv_bfloat16* __restrict__ Bo,
                 const float* __restrict__ bias, void* __restrict__ Cout,
                 int M, int N, int K) {
    extern __shared__ uint32_t smem[];
    hmma_gemm_body<EPI>(A, Bo, bias, Cout, M, N, K,
                        blockIdx.y * BM, blockIdx.x * BN, smem);
}

// Dual GEMM: z=0 VAL (bf16 out), z=1 AWOFF (fp32 out).
__global__ void __launch_bounds__(256, 2)
hmma_gemm_dual_kernel(const __nv_bfloat16* __restrict__ A0, const __nv_bfloat16* __restrict__ B0,
                      const float* __restrict__ bias0, void* __restrict__ C0,
                      const __nv_bfloat16* __restrict__ A1, const __nv_bfloat16* __restrict__ B1,
                      const float* __restrict__ bias1, void* __restrict__ C1,
                      int M, int N, int K) {
    extern __shared__ uint32_t smem[];
    if (blockIdx.z == 0)
        hmma_gemm_body<3>(A0, B0, bias0, C0, M, N, K,
                          blockIdx.y * BM, blockIdx.x * BN, smem);
    else
        hmma_gemm_body<1>(A1, B1, bias1, C1, M, N, K,
                          blockIdx.y * BM, blockIdx.x * BN, smem);
}

// ------ all-weights convert: fp32 -> bf16 k-octet interleaved, 1 launch ----
__global__ void convert_all_kernel(const float* __restrict__ W1, const float* __restrict__ W2,
                                   const float* __restrict__ Wo, const float* __restrict__ Wv,
                                   __nv_bfloat16* __restrict__ W1h,
                                   __nv_bfloat16* __restrict__ W2h,
                                   __nv_bfloat16* __restrict__ Woh,
                                   __nv_bfloat16* __restrict__ Wvh) {
    int seg = blockIdx.y;
    int Kdim, Ndim;
    const float* W;
    __nv_bfloat16* Wh;
    if (seg < 2)      { Kdim = D;   Ndim = DFF; W = W1 + (size_t)seg * D * DFF;       Wh = W1h + (size_t)seg * D * DFF; }
    else if (seg < 4) { Kdim = DFF; Ndim = D;   W = W2 + (size_t)(seg - 2) * DFF * D; Wh = W2h + (size_t)(seg - 2) * DFF * D; }
    else if (seg < 6) { Kdim = D;   Ndim = D;   W = Wo + (size_t)(seg - 4) * D * D;   Wh = Woh + (size_t)(seg - 4) * D * D; }
    else              { Kdim = D;   Ndim = D;   W = Wv + (size_t)(seg - 6) * D * D;   Wh = Wvh + (size_t)(seg - 6) * D * D; }
    int i = blockIdx.x * blockDim.x + threadIdx.x;
    int total = (Kdim / 8) * Ndim;
    if (i >= total) return;
    int chunk = i / Ndim, n = i % Ndim;
    __nv_bfloat162 o[4];
#pragma unroll
    for (int j = 0; j < 4; j++) {
        float a = W[(size_t)(chunk * 8 + 2 * j)     * Ndim + n];
        float b = W[(size_t)(chunk * 8 + 2 * j + 1) * Ndim + n];
        o[j] = __floats2bfloat162_rn(a, b);
    }
    uint4 v;
    v.x = *(uint32_t*)&o[0]; v.y = *(uint32_t*)&o[1];
    v.z = *(uint32_t*)&o[2]; v.w = *(uint32_t*)&o[3];
    *(uint4*)(Wh + (size_t)i * 8) = v;
}

// ------ merged attn+box weights -> bf16 k-octet, padded to 256, 2 layers ---
__global__ void concat_wb_bf16_kernel(const float* __restrict__ Wattn, const float* __restrict__ battn,
                                      const float* __restrict__ Wbox,  const float* __restrict__ bbox,
                                      __nv_bfloat16* __restrict__ WCh, float* __restrict__ BC) {
    int chunk = blockIdx.x;
    int li    = blockIdx.y;
    int n     = threadIdx.x;
    const float* Wa = Wattn + (size_t)li * D * (NH * K2);
    const float* Wb = Wbox  + (size_t)li * D * (NH * 4);
    __nv_bfloat162 o[4];
#pragma unroll
    for (int j = 0; j < 4; j++) {
        float a = 0.f, b = 0.f;
        int k0 = chunk * 8 + 2 * j;
        if (n < NH * K2) {
            a = Wa[(size_t)k0 * (NH * K2) + n];
            b = Wa[(size_t)(k0 + 1) * (NH * K2) + n];
        } else if (n < NCAT) {
            a = Wb[(size_t)k0 * (NH * 4) + (n - NH * K2)];
            b = Wb[(size_t)(k0 + 1) * (NH * 4) + (n - NH * K2)];
        }
        o[j] = __floats2bfloat162_rn(a, b);
    }
    uint4 v;
    v.x = *(uint32_t*)&o[0]; v.y = *(uint32_t*)&o[1];
    v.z = *(uint32_t*)&o[2]; v.w = *(uint32_t*)&o[3];
    *(uint4*)(WCh + ((size_t)li * (D / 8) * NCATP + (size_t)chunk * NCATP + n) * 8) = v;
    if (chunk == 0) {
        const float* ba = battn + (size_t)li * (NH * K2);
        const float* bb = bbox  + (size_t)li * (NH * 4);
        BC[li * NCATP + n] = (n < NH * K2) ? ba[n] : (n < NCAT ? bb[n - NH * K2] : 0.f);
    }
}

// --- fused transpose: (D,L)x2 -> X, P, Qh=bf16(X+P), Xh=bf16(X) (L,D) ------
__global__ void transpose2_kernel(const float* __restrict__ S, const float* __restrict__ Pp,
                                  float* __restrict__ X, float* __restrict__ P,
                                  __nv_bfloat16* __restrict__ Qh,
                                  __nv_bfloat16* __restrict__ Xh) {
    __shared__ float ts[32][33];
    __shared__ float tp[32][33];
    int bx = blockIdx.x * 32;
    int by = blockIdx.y * 32;
    int tx = threadIdx.x, ty = threadIdx.y;
#pragma unroll
    for (int j = 0; j < 32; j += 8) {
        ts[ty + j][tx] = S [(size_t)(by + ty + j) * L + bx + tx];
        tp[ty + j][tx] = Pp[(size_t)(by + ty + j) * L + bx + tx];
    }
    __syncthreads();
#pragma unroll
    for (int j = 0; j < 32; j += 8) {
        size_t o = (size_t)(bx + ty + j) * D + by + tx;
        float xs = ts[tx][ty + j];
        float ps = tp[tx][ty + j];
        X[o] = xs;
        P[o] = ps;
        Qh[o] = __float2bfloat16_rn(xs + ps);
        Xh[o] = __float2bfloat16_rn(xs);
    }
}

// ------------- smem-tiled deformable box sampling + fused softmax ----------
__global__ void __launch_bounds__(256, 3)
box_sample_tiled_kernel(const __nv_bfloat16* __restrict__ VAL,
                        const float* __restrict__ AWOFF,
                        __nv_bfloat16* __restrict__ OUT) {
    extern __shared__ float patch[];   // [PW*PW][32] fp32

    const int tile = blockIdx.x;
    const int h    = blockIdx.y;
    const int tx0  = (tile & 7) * TS;
    const int ty0  = (tile >> 3) * TS;
    const int xlo  = tx0 - PAD;
    const int ylo  = ty0 - PAD;
    const int tid  = threadIdx.x;
    const int warp = tid >> 5;
    const int lane = tid & 31;

    for (int i = tid; i < PW * PW * (HD / 8); i += 256) {
        int pix = i >> 2;
        int c8  = (i & 3) * 8;
        int py  = pix / PW, px = pix % PW;
        int gy  = min(max(ylo + py, 0), HDIM - 1);
        int gx  = min(max(xlo + px, 0), WDIM - 1);
        uint4 v = *(const uint4*)(VAL + (size_t)(gy * WDIM + gx) * D + h * HD + c8);
        float* dst = patch + pix * HD + c8;
        __nv_bfloat162 p0 = *(__nv_bfloat162*)&v.x;
        __nv_bfloat162 p1 = *(__nv_bfloat162*)&v.y;
        __nv_bfloat162 p2 = *(__nv_bfloat162*)&v.z;
        __nv_bfloat162 p3 = *(__nv_bfloat162*)&v.w;
        float2 f0 = __bfloat1622float2(p0);
        float2 f1 = __bfloat1622float2(p1);
        float2 f2 = __bfloat1622float2(p2);
        float2 f3 = __bfloat1622float2(p3);
        *(float4*)(dst)     = make_float4(f0.x, f0.y, f1.x, f1.y);
        *(float4*)(dst + 4) = make_float4(f2.x, f2.y, f3.x, f3.y);
    }
    __syncthreads();

    const __nv_bfloat16* vbase = VAL + h * HD + lane;
    const float scl = 0.025f * 0.125f;

    for (int it = 0; it < 32; it++) {
        int tt = warp * 32 + it;
        int r = tt >> 4, c = tt & 15;
        int gx = tx0 + c, gy = ty0 + r;
        int l = gy * WDIM + gx;

        const float* awl = AWOFF + (size_t)l * NCATP + h * K2;
        float lg = (lane < K2) ? awl[lane] : -1e30f;
        float mx = lg;
#pragma unroll
        for (int o = 16; o; o >>= 1) mx = fmaxf(mx, __shfl_xor_sync(0xFFFFFFFFu, mx, o));
        float e = (lane < K2) ? __expf(lg - mx) : 0.f;
        float s = e;
#pragma unroll
        for (int o = 16; o; o >>= 1) s += __shfl_xor_sync(0xFFFFFFFFu, s, o);
        float wsm = e / s;

        const float* off = AWOFF + (size_t)l * NCATP + NH * K2 + h * 4;
        float bx = (gx + 0.5f) * (1.f / WDIM) + off[0] * scl;
        float by = (gy + 0.5f) * (1.f / HDIM) + off[1] * scl;
        float bw = 0.025f + off[2] * scl;
        float bh = 0.025f + off[3] * scl;

        float acc = 0.f;
#pragma unroll
        for (int k = 0; k < K2; k++) {
            float a = __shfl_sync(0xFFFFFFFFu, wsm, k);
            float gxk = -0.5f + 0.25f * (k % 5);
            float gyk = -0.5f + 0.25f * (k / 5);
            float px = (bx + bw * gxk) * (float)WDIM - 0.5f;
            float py = (by + bh * gyk) * (float)HDIM - 0.5f;
            int ix0 = (int)floorf(px);
            int iy0 = (int)floorf(py);
            float fx = px - (float)ix0;
            float fy = py - (float)iy0;

            int lx = ix0 - xlo, ly = iy0 - ylo;
            bool inpatch = (lx >= 0) && (lx + 1 < PW) && (ly >= 0) && (ly + 1 < PW);

            float w00 = (1.f - fx) * (1.f - fy);
            float w10 = fx * (1.f - fy);
            float w01 = (1.f - fx) * fy;
            float w11 = fx * fy;
            bool vx0 = (ix0 >= 0) && (ix0 < WDIM);
            bool vx1 = (ix0 + 1 >= 0) && (ix0 + 1 < WDIM);
            bool vy0 = (iy0 >= 0) && (iy0 < HDIM);
            bool vy1 = (iy0 + 1 >= 0) && (iy0 + 1 < HDIM);
            w00 = (vx0 && vy0) ? w00 : 0.f;
            w10 = (vx1 && vy0) ? w10 : 0.f;
            w01 = (vx0 && vy1) ? w01 : 0.f;
            w11 = (vx1 && vy1) ? w11 : 0.f;

            if (inpatch) {
                const float* p00 = patch + (ly * PW + lx) * HD + lane;
                float v00 = p00[0];
                float v10 = p00[HD];
                float v01 = p00[PW * HD];
                float v11 = p00[PW * HD + HD];
                acc = fmaf(a, w00 * v00 + w10 * v10 + w01 * v01 + w11 * v11, acc);
            } else {
                int cx0 = min(max(ix0, 0), WDIM - 1);
                int cx1 = min(max(ix0 + 1, 0), WDIM - 1);
                int cy0 = min(max(iy0, 0), HDIM - 1);
                int cy1 = min(max(iy0 + 1, 0), HDIM - 1);
                float v00 = __bfloat162float(vbase[(size_t)(cy0 * WDIM + cx0) * D]);
                float v10 = __bfloat162float(vbase[(size_t)(cy0 * WDIM + cx1) * D]);
                float v01 = __bfloat162float(vbase[(size_t)(cy1 * WDIM + cx0) * D]);
                float v11 = __bfloat162float(vbase[(size_t)(cy1 * WDIM + cx1) * D]);
                acc = fmaf(a, w00 * v00 + w10 * v10 + w01 * v01 + w11 * v11, acc);
            }
        }
        OUT[(size_t)l * D + h * HD + lane] = __float2bfloat16_rn(acc);
    }
}

// -- fused residual + LayerNorm: Xin fp32 + Add bf16 (+opt Qh / bf16 copy) --
template <bool WRITE_Q, bool WRITE_H>
__global__ void ln_residual_kernel(const float* __restrict__ Xin,
                                   const __nv_bfloat16* __restrict__ Add,
                                   const float* __restrict__ gamma,
                                   const float* __restrict__ beta,
                                   float* __restrict__ Out,
                                   const float* __restrict__ P,
                                   __nv_bfloat16* __restrict__ Qh,
                                   __nv_bfloat16* __restrict__ Hout) {
    int row  = blockIdx.x * (blockDim.x >> 5) + (threadIdx.x >> 5);
    int lane = threadIdx.x & 31;
    if (row >= L) return;
    const size_t base = (size_t)row * D + lane * 8;

    float v[8];
    {
        float4 a0 = *(const float4*)(Xin + base);
        float4 a1 = *(const float4*)(Xin + base + 4);
        uint4 bb = *(const uint4*)(Add + base);
        __nv_bfloat162 b0 = *(__nv_bfloat162*)&bb.x;
        __nv_bfloat162 b1 = *(__nv_bfloat162*)&bb.y;
        __nv_bfloat162 b2 = *(__nv_bfloat162*)&bb.z;
        __nv_bfloat162 b3 = *(__nv_bfloat162*)&bb.w;
        float2 f0 = __bfloat1622float2(b0);
        float2 f1 = __bfloat1622float2(b1);
        float2 f2 = __bfloat1622float2(b2);
        float2 f3 = __bfloat1622float2(b3);
        v[0] = a0.x + f0.x; v[1] = a0.y + f0.y; v[2] = a0.z + f1.x; v[3] = a0.w + f1.y;
        v[4] = a1.x + f2.x; v[5] = a1.y + f2.y; v[6] = a1.z + f3.x; v[7] = a1.w + f3.y;
    }
    float s = 0.f;
#pragma unroll
    for (int i = 0; i < 8; i++) s += v[i];
#pragma unroll
    for (int o = 16; o; o >>= 1) s += __shfl_xor_sync(0xFFFFFFFFu, s, o);
    float m = s * (1.f / D);
    float vs = 0.f;
#pragma unroll
    for (int i = 0; i < 8; i++) { float d = v[i] - m; vs += d * d; }
#pragma unroll
    for (int o = 16; o; o >>= 1) vs += __shfl_xor_sync(0xFFFFFFFFu, vs, o);
    float rstd = rsqrtf(vs * (1.f / D) + EPS);

    float4 g0 = *(const float4*)(gamma + lane * 8);
    float4 g1 = *(const float4*)(gamma + lane * 8 + 4);
    float4 be0 = *(const float4*)(beta + lane * 8);
    float4 be1 = *(const float4*)(beta + lane * 8 + 4);
    float o[8];
    o[0] = (v[0] - m) * rstd * g0.x + be0.x;
    o[1] = (v[1] - m) * rstd * g0.y + be0.y;
    o[2] = (v[2] - m) * rstd * g0.z + be0.z;
    o[3] = (v[3] - m) * rstd * g0.w + be0.w;
    o[4] = (v[4] - m) * rstd * g1.x + be1.x;
    o[5] = (v[5] - m) * rstd * g1.y + be1.y;
    o[6] = (v[6] - m) * rstd * g1.z + be1.z;
    o[7] = (v[7] - m) * rstd * g1.w + be1.w;

    *(float4*)(Out + base)     = make_float4(o[0], o[1], o[2], o[3]);
    *(float4*)(Out + base + 4) = make_float4(o[4], o[5], o[6], o[7]);
    if (WRITE_Q) {
        float4 p0 = *(const float4*)(P + base);
        float4 p1 = *(const float4*)(P + base + 4);
        uint4 q;
        __nv_bfloat162 q0 = __floats2bfloat162_rn(o[0] + p0.x, o[1] + p0.y);
        __nv_bfloat162 q1 = __floats2bfloat162_rn(o[2] + p0.z, o[3] + p0.w);
        __nv_bfloat162 q2 = __floats2bfloat162_rn(o[4] + p1.x, o[5] + p1.y);
        __nv_bfloat162 q3 = __floats2bfloat162_rn(o[6] + p1.z, o[7] + p1.w);
        q.x = *(uint32_t*)&q0; q.y = *(uint32_t*)&q1;
        q.z = *(uint32_t*)&q2; q.w = *(uint32_t*)&q3;
        *(uint4*)(Qh + base) = q;
    }
    if (WRITE_H) {
        uint4 h;
        __nv_bfloat162 h0 = __floats2bfloat162_rn(o[0], o[1]);
        __nv_bfloat162 h1 = __floats2bfloat162_rn(o[2], o[3]);
        __nv_bfloat162 h2 = __floats2bfloat162_rn(o[4], o[5]);
        __nv_bfloat162 h3 = __floats2bfloat162_rn(o[6], o[7]);
        h.x = *(uint32_t*)&h0; h.y = *(uint32_t*)&h1;
        h.z = *(uint32_t*)&h2; h.w = *(uint32_t*)&h3;
        *(uint4*)(Hout + base) = h;
    }
}

// ------------------------- host-side launchers -----------------------------
template <int EPI>
static void launch_hmma_gemm(const __nv_bfloat16* A, const __nv_bfloat16* Bo,
                             const float* bias, void* C, int M, int N, int K) {
    cudaFuncSetAttribute(hmma_gemm_kernel<EPI>,
                         cudaFuncAttributeMaxDynamicSharedMemorySize, HGEMM_SMEM);
    dim3 grid(N / BN, M / BM);
    hmma_gemm_kernel<EPI><<<grid, 256, HGEMM_SMEM>>>(A, Bo, bias, C, M, N, K);
}

extern "C" void kernel_launch(void* const* d_in, const int* in_sizes, int n_in,
                              void* d_out, int out_size) {
    const float* src   = (const float*)d_in[0];
    const float* pos   = (const float*)d_in[1];
    const float* Wv    = (const float*)d_in[2];
    const float* bv    = (const float*)d_in[3];
    const float* Wbox  = (const float*)d_in[4];
    const float* bbox  = (const float*)d_in[5];
    const float* Wattn = (const float*)d_in[6];
    const float* battn = (const float*)d_in[7];
    const float* Wo    = (const float*)d_in[8];
    const float* bo    = (const float*)d_in[9];
    const float* W1    = (const float*)d_in[10];
    const float* b1    = (const float*)d_in[11];
    const float* W2    = (const float*)d_in[12];
    const float* b2    = (const float*)d_in[13];
    const float* ln1_g = (const float*)d_in[14];
    const float* ln1_b = (const float*)d_in[15];
    const float* ln2_g = (const float*)d_in[16];
    const float* ln2_b = (const float*)d_in[17];

    float *X, *P, *AWOFF, *BCAT;
    __nv_bfloat16 *TMPh, *VALh, *Qh, *OUTh, *Xh, *FFh, *WCATh, *W1h, *W2h, *Woh, *Wvh;
    cudaGetSymbolAddress((void**)&X,     g_X);
    cudaGetSymbolAddress((void**)&P,     g_P);
    cudaGetSymbolAddress((void**)&AWOFF, g_AWOFF);
    cudaGetSymbolAddress((void**)&BCAT,  g_BCAT);
    cudaGetSymbolAddress((void**)&TMPh,  g_TMPh);
    cudaGetSymbolAddress((void**)&VALh,  g_VALh);
    cudaGetSymbolAddress((void**)&Qh,    g_Qh);
    cudaGetSymbolAddress((void**)&OUTh,  g_OUTh);
    cudaGetSymbolAddress((void**)&Xh,    g_Xh);
    cudaGetSymbolAddress((void**)&FFh,   g_FFh);
    cudaGetSymbolAddress((void**)&WCATh, g_WCATh);
    cudaGetSymbolAddress((void**)&W1h,   g_W1h);
    cudaGetSymbolAddress((void**)&W2h,   g_W2h);
    cudaGetSymbolAddress((void**)&Woh,   g_Woh);
    cudaGetSymbolAddress((void**)&Wvh,   g_Wvh);

    cudaFuncSetAttribute(box_sample_tiled_kernel,
                         cudaFuncAttributeMaxDynamicSharedMemorySize, SAMP_SMEM);
    cudaFuncSetAttribute(hmma_gemm_dual_kernel,
                         cudaFuncAttributeMaxDynamicSharedMemorySize, HGEMM_SMEM);

    {
        dim3 tb(32, 8);
        dim3 tg(L / 32, D / 32);
        transpose2_kernel<<<tg, tb>>>(src, pos, X, P, Qh, Xh);
    }
    {
        dim3 cg(((D / 8) * DFF + 255) / 256, 8);
        convert_all_kernel<<<cg, 256>>>(W1, W2, Wo, Wv, W1h, W2h, Woh, Wvh);
        dim3 kg(D / 8, 2);
        concat_wb_bf16_kernel<<<kg, NCATP>>>(Wattn, battn, Wbox, bbox, WCATh, BCAT);
    }

    for (int i = 0; i < 2; i++) {
        const float* bv_i    = bv    + (size_t)i * D;
        const float* bo_i    = bo    + (size_t)i * D;
        const float* b1_i    = b1    + (size_t)i * DFF;
        const float* b2_i    = b2    + (size_t)i * D;
        const float* ln1g_i  = ln1_g + (size_t)i * D;
        const float* ln1b_i  = ln1_b + (size_t)i * D;
        const float* ln2g_i  = ln2_g + (size_t)i * D;
        const float* ln2b_i  = ln2_b + (size_t)i * D;

        // fused dual GEMM: VALh = bf16(Xh @ Wv + bv) ; AWOFF = Qh @ WCAT + BCAT
        {
            dim3 grid(D / BN, L / BM, 2);
            hmma_gemm_dual_kernel<<<grid, 256, HGEMM_SMEM>>>(
                Xh, Wvh + (size_t)i * D * D, bv_i, VALh,
                Qh, WCATh + (size_t)i * D * NCATP, BCAT + i * NCATP, AWOFF,
                L, D, D);
        }

        {
            dim3 sg(64, NH);
            box_sample_tiled_kernel<<<sg, 256, SAMP_SMEM>>>(VALh, AWOFF, OUTh);
        }

        // a = OUT @ Wo + bo (bf16 out)
        launch_hmma_gemm<3>(OUTh, Woh + (size_t)i * D * D, bo_i, TMPh, L, D, D);
        ln_residual_kernel<false, true><<<L / 8, 256>>>(X, TMPh, ln1g_i, ln1b_i, X,
                                                        nullptr, nullptr, Xh);

        launch_hmma_gemm<2>(Xh, W1h + (size_t)i * D * DFF, b1_i, FFh, L, DFF, D);
        launch_hmma_gemm<3>(FFh, W2h + (size_t)i * DFF * D, b2_i, TMPh, L, D, DFF);

        if (i == 0) {
            ln_residual_kernel<true, true><<<L / 8, 256>>>(X, TMPh, ln2g_i, ln2b_i, X,
                                                           P, Qh, Xh);
        } else {
            ln_residual_kernel<false, false><<<L / 8, 256>>>(X, TMPh, ln2g_i, ln2b_i,
                                                             (float*)d_out,
                                                             nullptr, nullptr, nullptr);
        }
    }
}